// round 4
// baseline (speedup 1.0000x reference)
#include <cuda_runtime.h>
#include <cstdint>

#define BATCH   16
#define NANCH   25200
#define NCH     85
#define NCLS    80
#define TOPK    1024
#define MAXDET  300
#define CONF_THR 0.6f
#define IOU_THR  0.45f
#define OFFS     4096.0f
#define NBINS    4096
#define CHUNK    256          // mask rows staged per smem chunk in k_out

// ---------------- static device scratch (no allocations allowed) ----------------
__device__ float         g_score[BATCH * NANCH];
__device__ unsigned char g_cls[BATCH * NANCH];
__device__ int           g_topk_idx[BATCH * TOPK];
__device__ float         g_topk_score[BATCH * TOPK];
__device__ float4        g_nmsbox[BATCH * TOPK];
__device__ unsigned int  g_mask[BATCH * TOPK * 32];

// ---------------- K1: per-anchor score / class (warp per anchor) ----------------
__global__ void k_score(const float* __restrict__ pred) {
    int gwarp = (blockIdx.x * blockDim.x + threadIdx.x) >> 5;
    int lane  = threadIdx.x & 31;
    if (gwarp >= BATCH * NANCH) return;
    const float* base = pred + (size_t)gwarp * NCH;
    float obj = base[4];
    // products first (matches reference: cls_scores = pred[5:] * obj, then max/argmax)
    float best = -2.0f; int bidx = 0;
    #pragma unroll
    for (int r = 0; r < 3; r++) {
        int j = lane + 32 * r;
        if (j < NCLS) {
            float p = __fmul_rn(obj, base[5 + j]);
            if (p > best) { best = p; bidx = j; }   // strict > keeps lower index on tie
        }
    }
    #pragma unroll
    for (int off = 16; off > 0; off >>= 1) {
        float ob = __shfl_down_sync(0xffffffffu, best, off);
        int   oi = __shfl_down_sync(0xffffffffu, bidx, off);
        if (ob > best || (ob == best && oi < bidx)) { best = ob; bidx = oi; }
    }
    if (lane == 0) {
        bool valid = (obj > CONF_THR) && (best > CONF_THR);
        g_score[gwarp] = valid ? best : -1.0f;
        g_cls[gwarp]   = (unsigned char)bidx;
    }
}

// ---------------- K2: per-image exact top-1024 via histogram + bitonic sort -----
__global__ void k_select(const float* __restrict__ pred) {
    int b   = blockIdx.x;
    int tid = threadIdx.x;                 // 1024 threads
    __shared__ int hist[NBINS];
    __shared__ unsigned long long sbuf[2 * TOPK];
    __shared__ int partial[1024];
    __shared__ int sup[32];
    __shared__ int sh_T;
    __shared__ int counter;

    for (int i = tid; i < NBINS; i += 1024) hist[i] = 0;
    if (tid == 0) counter = 0;
    __syncthreads();

    const float* sc = g_score + (size_t)b * NANCH;
    const float kBinScale = (float)NBINS / 0.4f;

    for (int i = tid; i < NANCH; i += 1024) {
        float s = sc[i];
        if (s > CONF_THR) {
            int bin = (int)((s - CONF_THR) * kBinScale);
            bin = min(max(bin, 0), NBINS - 1);
            atomicAdd(&hist[bin], 1);
        }
    }
    __syncthreads();

    int ps = 0;
    #pragma unroll
    for (int k = 0; k < 4; k++) ps += hist[4 * tid + k];
    partial[tid] = ps;
    __syncthreads();

    if (tid < 32) {
        int s = 0;
        for (int g = 0; g < 32; g++) s += partial[32 * tid + g];
        sup[tid] = s;
        __syncwarp();
        if (tid == 0) {
            int acc = 0, T = 0, l;
            for (l = 31; l >= 0; l--) { if (acc + sup[l] >= TOPK) break; acc += sup[l]; }
            if (l >= 0) {
                int g;
                for (g = 31; g >= 0; g--) { int v = partial[32 * l + g]; if (acc + v >= TOPK) break; acc += v; }
                if (g < 0) g = 0;
                int bb;
                for (bb = 3; bb >= 0; bb--) { int v = hist[4 * (32 * l + g) + bb]; if (acc + v >= TOPK) break; acc += v; }
                if (bb < 0) bb = 0;
                T = 4 * (32 * l + g) + bb;
            }
            sh_T = T;
        }
    }
    __syncthreads();
    int T = sh_T;

    for (int i = tid; i < NANCH; i += 1024) {
        float s = sc[i];
        if (s > CONF_THR) {
            int bin = (int)((s - CONF_THR) * kBinScale);
            bin = min(max(bin, 0), NBINS - 1);
            if (bin >= T) {
                int pos = atomicAdd(&counter, 1);
                if (pos < 2 * TOPK) {
                    unsigned int u = __float_as_uint(s) ^ 0x80000000u;  // positive float -> order-preserving
                    sbuf[pos] = (((unsigned long long)(~u)) << 32) | (unsigned int)i;
                }
            }
        }
    }
    __syncthreads();
    int M = min(counter, 2 * TOPK);
    for (int i = tid; i < 2 * TOPK; i += 1024)
        if (i >= M) sbuf[i] = 0xFFFFFFFFFFFFFFFFull;
    __syncthreads();

    // bitonic sort ascending: primary ~score_bits (=> score descending), ties idx ascending
    for (int k = 2; k <= 2 * TOPK; k <<= 1) {
        for (int j = k >> 1; j > 0; j >>= 1) {
            for (int e = tid; e < 2 * TOPK; e += 1024) {
                int partner = e ^ j;
                if (partner > e) {
                    bool asc = ((e & k) == 0);
                    unsigned long long a = sbuf[e], c = sbuf[partner];
                    if ((a > c) == asc) { sbuf[e] = c; sbuf[partner] = a; }
                }
            }
            __syncthreads();
        }
    }

    // emit top-1024: idx, score, class-offset nms box
    if (tid < TOPK) {
        int slot = b * TOPK + tid;
        if (tid < M) {
            unsigned long long key = sbuf[tid];
            int idx = (int)(key & 0xFFFFFFFFu);
            unsigned int u = ~((unsigned int)(key >> 32));
            float s = __uint_as_float(u ^ 0x80000000u);
            g_topk_score[slot] = s;
            g_topk_idx[slot]   = idx;
            const float* p = pred + ((size_t)b * NANCH + idx) * NCH;
            float cx = p[0], cy = p[1], w = p[2], h = p[3];
            float hw = __fmul_rn(w, 0.5f), hh = __fmul_rn(h, 0.5f);
            float x1 = __fsub_rn(cx, hw), y1 = __fsub_rn(cy, hh);
            float x2 = __fadd_rn(cx, hw), y2 = __fadd_rn(cy, hh);
            float off = __fmul_rn((float)g_cls[(size_t)b * NANCH + idx], OFFS);
            g_nmsbox[slot] = make_float4(__fadd_rn(x1, off), __fadd_rn(y1, off),
                                         __fadd_rn(x2, off), __fadd_rn(y2, off));
        } else {
            g_topk_score[slot] = -1.0f;
            g_topk_idx[slot]   = 0;
            float far = -1.0e9f - (float)tid * 16.0f;   // inert: never kept, never suppresses
            g_nmsbox[slot] = make_float4(far, far, far + 1.0f, far + 1.0f);
        }
    }
}

// ---------------- K3: suppression bitmask; div only when inter > 0 -------------
__global__ void k_mask() {
    int b = blockIdx.x, q = blockIdx.y;     // q in [0,8): column eighth (128 cols)
    int i = threadIdx.x;                    // 1024 threads, one row each
    __shared__ float4 boxes[TOPK];
    __shared__ float  areas[TOPK];
    for (int t = threadIdx.x; t < TOPK; t += 1024) {
        float4 v = g_nmsbox[b * TOPK + t];
        boxes[t] = v;
        areas[t] = __fmul_rn(__fsub_rn(v.z, v.x), __fsub_rn(v.w, v.y));
    }
    __syncthreads();

    float4 bi = boxes[i];
    float area_i = areas[i];
    int j0 = q * 128;
    #pragma unroll
    for (int w = 0; w < 4; w++) {
        unsigned int m = 0;
        #pragma unroll 4
        for (int t = 0; t < 32; t++) {
            int j = j0 + w * 32 + t;
            if (j > i) {
                float4 bj = boxes[j];
                float ltx = fmaxf(bi.x, bj.x), lty = fmaxf(bi.y, bj.y);
                float rbx = fminf(bi.z, bj.z), rby = fminf(bi.w, bj.w);
                float wx = fmaxf(__fsub_rn(rbx, ltx), 0.0f);
                float wy = fmaxf(__fsub_rn(rby, lty), 0.0f);
                float inter = __fmul_rn(wx, wy);
                if (inter > 0.0f) {         // inter==0 -> iou==+0, never > 0.45
                    float denom = __fadd_rn(__fsub_rn(__fadd_rn(area_i, areas[j]), inter), 1e-9f);
                    float iou = inter / denom;
                    if (iou > IOU_THR) m |= (1u << t);
                }
            }
        }
        g_mask[((size_t)b * TOPK + i) * 32 + q * 4 + w] = m;
    }
}

// ---------------- K4: single-thread register greedy walk + parallel emit --------
__global__ void k_out(const float* __restrict__ pred,
                      const float* __restrict__ logits,
                      float* __restrict__ out) {
    int b   = blockIdx.x;
    int tid = threadIdx.x;                  // 1024 threads
    __shared__ float              s_score[TOPK];            // 4 KB
    __shared__ unsigned long long s_mask64[CHUNK * 16];     // 32 KB staged mask rows
    __shared__ int sel[MAXDET];
    __shared__ int sh_count;
    __shared__ int sh_stop;

    if (tid < TOPK) s_score[tid] = g_topk_score[b * TOPK + tid];
    if (tid == 0) { sh_stop = 0; sh_count = 0; }

    const unsigned long long* gmask =
        (const unsigned long long*)(g_mask + (size_t)b * TOPK * 32);

    // thread 0's removed-bit set, fully register resident (constant indexing only)
    unsigned long long rem[16];
    #pragma unroll
    for (int w = 0; w < 16; w++) rem[w] = 0ull;
    int count = 0;

    #pragma unroll
    for (int c = 0; c < TOPK / CHUNK; c++) {
        __syncthreads();                    // publish sh_stop; walk done before overwrite
        int stop = sh_stop;
        if (!stop) {
            #pragma unroll
            for (int t = 0; t < (CHUNK * 16) / 1024; t++)   // 4 u64 per thread, coalesced
                s_mask64[t * 1024 + tid] = gmask[(size_t)c * (CHUNK * 16) + t * 1024 + tid];
        }
        __syncthreads();
        if (stop) continue;

        if (tid == 0) {
            bool halt = false;
            #pragma unroll
            for (int u = 0; u < CHUNK / 64; u++) {          // 4 u64 words per chunk
                if (!halt) {
                    for (int bit = 0; bit < 64; bit++) {
                        int i = c * CHUNK + u * 64 + bit;
                        float s = s_score[i];
                        if (s <= CONF_THR) { halt = true; break; }
                        if (!((rem[c * 4 + u] >> bit) & 1ull)) {
                            const unsigned long long* mrow = &s_mask64[(size_t)(i & (CHUNK - 1)) * 16];
                            #pragma unroll
                            for (int w = 0; w < 16; w++) rem[w] |= mrow[w];
                            sel[count] = i;
                            count++;
                            if (count == MAXDET) { halt = true; break; }
                        }
                    }
                }
            }
            if (halt) sh_stop = 1;
            sh_count = count;
        }
    }
    __syncthreads();
    count = sh_count;

    float* det  = out;                                      // [B,300,6]
    float* vout = out + BATCH * MAXDET * 6;                 // [B,300]
    float* lout = vout + BATCH * MAXDET;                    // [B,300,80]

    for (int s = tid; s < MAXDET; s += 1024) {
        float d0 = 0, d1 = 0, d2 = 0, d3 = 0, d4 = 0, d5 = 0, v = 0;
        if (s < count) {
            int i   = sel[s];
            int idx = g_topk_idx[b * TOPK + i];
            const float* p = pred + ((size_t)b * NANCH + idx) * NCH;
            float cx = p[0], cy = p[1], w = p[2], h = p[3];
            float hw = __fmul_rn(w, 0.5f), hh = __fmul_rn(h, 0.5f);
            d0 = __fsub_rn(cx, hw); d1 = __fsub_rn(cy, hh);
            d2 = __fadd_rn(cx, hw); d3 = __fadd_rn(cy, hh);
            d4 = s_score[i];
            d5 = (float)g_cls[(size_t)b * NANCH + idx];
            v = 1.0f;
        }
        float* dr = det + ((size_t)b * MAXDET + s) * 6;
        dr[0] = d0; dr[1] = d1; dr[2] = d2; dr[3] = d3; dr[4] = d4; dr[5] = d5;
        vout[b * MAXDET + s] = v;
    }

    for (int e = tid; e < MAXDET * NCLS; e += 1024) {
        int s = e / NCLS, c = e % NCLS;
        float v = 0.0f;
        if (s < count) {
            int i   = sel[s];
            int idx = g_topk_idx[b * TOPK + i];
            v = logits[((size_t)b * NANCH + idx) * NCLS + c];
        }
        lout[((size_t)b * MAXDET + s) * NCLS + c] = v;
    }
}

// ---------------- launch --------------------------------------------------------
extern "C" void kernel_launch(void* const* d_in, const int* in_sizes, int n_in,
                              void* d_out, int out_size) {
    (void)in_sizes; (void)n_in; (void)out_size;
    const float* pred   = (const float*)d_in[0];
    const float* logits = (const float*)d_in[1];
    float* out = (float*)d_out;

    int total_warps = BATCH * NANCH;                 // one warp per anchor
    int blocks = (total_warps + 7) / 8;              // 256 threads = 8 warps per block
    k_score<<<blocks, 256>>>(pred);
    k_select<<<BATCH, 1024>>>(pred);
    k_mask<<<dim3(BATCH, 8), 1024>>>();
    k_out<<<BATCH, 1024>>>(pred, logits, out);
}

// round 6
// speedup vs baseline: 1.7512x; 1.7512x over previous
#include <cuda_runtime.h>
#include <cstdint>

#define BATCH   16
#define NANCH   25200
#define NCH     85
#define NCLS    80
#define TOPK    1024
#define MAXDET  300
#define CONF_THR 0.6f
#define IOU_THR  0.45f
#define OFFS     4096.0f
#define NBINS    4096
#define APB      128          // anchors per block in k_score

// ---------------- static device scratch (no allocations allowed) ----------------
__device__ float         g_score[BATCH * NANCH];
__device__ unsigned char g_cls[BATCH * NANCH];
__device__ int           g_topk_idx[BATCH * TOPK];
__device__ float         g_topk_score[BATCH * TOPK];
__device__ float4        g_nmsbox[BATCH * TOPK];
__device__ __align__(16) unsigned int g_mask[BATCH * TOPK * 32];

// ---------------- K1: smem-tiled score / class (thread per anchor) --------------
__global__ void k_score(const float* __restrict__ pred) {
    __shared__ float sp[APB * NCH];            // 43520 B
    int b  = blockIdx.y;
    int a0 = blockIdx.x * APB;
    int tid = threadIdx.x;                     // 256 threads
    int cnt = min(APB, NANCH - a0);            // 128 or 112; both %4==0
    int n4  = (cnt * NCH) >> 2;                // float4 count (divisible)

    const float4* src = (const float4*)(pred + ((size_t)b * NANCH + a0) * NCH);
    float4* dst = (float4*)sp;
    for (int i = tid; i < n4; i += 256) dst[i] = src[i];
    __syncthreads();

    if (tid < cnt) {
        const float* row = sp + tid * NCH;
        float obj = row[4];
        float best = -2.0f; int bidx = 0;
        #pragma unroll 8
        for (int j = 0; j < NCLS; j++) {
            float p = __fmul_rn(obj, row[5 + j]);
            if (p > best) { best = p; bidx = j; }   // strict > = first max (jnp.argmax)
        }
        bool valid = (obj > CONF_THR) && (best > CONF_THR);
        int ga = b * NANCH + a0 + tid;
        g_score[ga] = valid ? best : -1.0f;
        g_cls[ga]   = (unsigned char)bidx;
    }
}

// ---------------- K2: per-image exact top-1024 via histogram + bitonic sort -----
__global__ void k_select(const float* __restrict__ pred) {
    int b   = blockIdx.x;
    int tid = threadIdx.x;                 // 1024 threads
    __shared__ int hist[NBINS];
    __shared__ unsigned long long sbuf[2 * TOPK];
    __shared__ int partial[1024];
    __shared__ int sup[32];
    __shared__ int sh_T;
    __shared__ int counter;

    for (int i = tid; i < NBINS; i += 1024) hist[i] = 0;
    if (tid == 0) counter = 0;
    __syncthreads();

    const float* sc = g_score + (size_t)b * NANCH;
    const float kBinScale = (float)NBINS / 0.4f;

    for (int i = tid; i < NANCH; i += 1024) {
        float s = sc[i];
        if (s > CONF_THR) {
            int bin = (int)((s - CONF_THR) * kBinScale);
            bin = min(max(bin, 0), NBINS - 1);
            atomicAdd(&hist[bin], 1);
        }
    }
    __syncthreads();

    int ps = 0;
    #pragma unroll
    for (int k = 0; k < 4; k++) ps += hist[4 * tid + k];
    partial[tid] = ps;
    __syncthreads();

    if (tid < 32) {
        int s = 0;
        for (int g = 0; g < 32; g++) s += partial[32 * tid + g];
        sup[tid] = s;
        __syncwarp();
        if (tid == 0) {
            int acc = 0, T = 0, l;
            for (l = 31; l >= 0; l--) { if (acc + sup[l] >= TOPK) break; acc += sup[l]; }
            if (l >= 0) {
                int g;
                for (g = 31; g >= 0; g--) { int v = partial[32 * l + g]; if (acc + v >= TOPK) break; acc += v; }
                if (g < 0) g = 0;
                int bb;
                for (bb = 3; bb >= 0; bb--) { int v = hist[4 * (32 * l + g) + bb]; if (acc + v >= TOPK) break; acc += v; }
                if (bb < 0) bb = 0;
                T = 4 * (32 * l + g) + bb;
            }
            sh_T = T;
        }
    }
    __syncthreads();
    int T = sh_T;

    for (int i = tid; i < NANCH; i += 1024) {
        float s = sc[i];
        if (s > CONF_THR) {
            int bin = (int)((s - CONF_THR) * kBinScale);
            bin = min(max(bin, 0), NBINS - 1);
            if (bin >= T) {
                int pos = atomicAdd(&counter, 1);
                if (pos < 2 * TOPK) {
                    unsigned int u = __float_as_uint(s) ^ 0x80000000u;  // order-preserving
                    sbuf[pos] = (((unsigned long long)(~u)) << 32) | (unsigned int)i;
                }
            }
        }
    }
    __syncthreads();
    int M = min(counter, 2 * TOPK);
    for (int i = tid; i < 2 * TOPK; i += 1024)
        if (i >= M) sbuf[i] = 0xFFFFFFFFFFFFFFFFull;
    __syncthreads();

    // bitonic sort ascending: primary ~score_bits (=> score descending), ties idx ascending
    for (int k = 2; k <= 2 * TOPK; k <<= 1) {
        for (int j = k >> 1; j > 0; j >>= 1) {
            for (int e = tid; e < 2 * TOPK; e += 1024) {
                int partner = e ^ j;
                if (partner > e) {
                    bool asc = ((e & k) == 0);
                    unsigned long long a = sbuf[e], c = sbuf[partner];
                    if ((a > c) == asc) { sbuf[e] = c; sbuf[partner] = a; }
                }
            }
            __syncthreads();
        }
    }

    // emit top-1024: idx, score, class-offset nms box
    if (tid < TOPK) {
        int slot = b * TOPK + tid;
        if (tid < M) {
            unsigned long long key = sbuf[tid];
            int idx = (int)(key & 0xFFFFFFFFu);
            unsigned int u = ~((unsigned int)(key >> 32));
            float s = __uint_as_float(u ^ 0x80000000u);
            g_topk_score[slot] = s;
            g_topk_idx[slot]   = idx;
            const float* p = pred + ((size_t)b * NANCH + idx) * NCH;
            float cx = p[0], cy = p[1], w = p[2], h = p[3];
            float hw = __fmul_rn(w, 0.5f), hh = __fmul_rn(h, 0.5f);
            float x1 = __fsub_rn(cx, hw), y1 = __fsub_rn(cy, hh);
            float x2 = __fadd_rn(cx, hw), y2 = __fadd_rn(cy, hh);
            float off = __fmul_rn((float)g_cls[(size_t)b * NANCH + idx], OFFS);
            g_nmsbox[slot] = make_float4(__fadd_rn(x1, off), __fadd_rn(y1, off),
                                         __fadd_rn(x2, off), __fadd_rn(y2, off));
        } else {
            g_topk_score[slot] = -1.0f;
            g_topk_idx[slot]   = 0;
            float far = -1.0e9f - (float)tid * 16.0f;   // inert: never kept, never suppresses
            g_nmsbox[slot] = make_float4(far, far, far + 1.0f, far + 1.0f);
        }
    }
}

// ---------------- K3: suppression bitmask; div only when inter > 0 -------------
__global__ void k_mask() {
    int b = blockIdx.x, q = blockIdx.y;     // q in [0,8): column eighth (128 cols)
    int i = threadIdx.x;                    // 1024 threads, one row each
    __shared__ float4 boxes[TOPK];
    __shared__ float  areas[TOPK];
    for (int t = threadIdx.x; t < TOPK; t += 1024) {
        float4 v = g_nmsbox[b * TOPK + t];
        boxes[t] = v;
        areas[t] = __fmul_rn(__fsub_rn(v.z, v.x), __fsub_rn(v.w, v.y));
    }
    __syncthreads();

    float4 bi = boxes[i];
    float area_i = areas[i];
    int j0 = q * 128;
    #pragma unroll
    for (int w = 0; w < 4; w++) {
        unsigned int m = 0;
        #pragma unroll 4
        for (int t = 0; t < 32; t++) {
            int j = j0 + w * 32 + t;
            if (j > i) {
                float4 bj = boxes[j];
                float ltx = fmaxf(bi.x, bj.x), lty = fmaxf(bi.y, bj.y);
                float rbx = fminf(bi.z, bj.z), rby = fminf(bi.w, bj.w);
                float wx = fmaxf(__fsub_rn(rbx, ltx), 0.0f);
                float wy = fmaxf(__fsub_rn(rby, lty), 0.0f);
                float inter = __fmul_rn(wx, wy);
                if (inter > 0.0f) {         // inter==0 -> iou==+0, never > 0.45
                    float denom = __fadd_rn(__fsub_rn(__fadd_rn(area_i, areas[j]), inter), 1e-9f);
                    float iou = inter / denom;
                    if (iou > IOU_THR) m |= (1u << t);
                }
            }
        }
        g_mask[((size_t)b * TOPK + i) * 32 + q * 4 + w] = m;
    }
}

// ---------------- K4: full-mask smem + ffs-driven greedy walk -------------------
__global__ void k_out(const float* __restrict__ pred,
                      const float* __restrict__ logits,
                      float* __restrict__ out) {
    extern __shared__ unsigned char dyn[];
    unsigned long long* s_mask = (unsigned long long*)dyn;          // TOPK*16 u64 = 128 KB
    float* s_score = (float*)(dyn + TOPK * 16 * sizeof(unsigned long long)); // 4 KB
    __shared__ int sel[MAXDET];
    __shared__ int sh_count;

    int b   = blockIdx.x;
    int tid = threadIdx.x;                  // 1024 threads

    float myscore = g_topk_score[b * TOPK + tid];
    s_score[tid] = myscore;

    // stage entire mask: 8192 ulonglong2 -> 8 per thread, coalesced
    const ulonglong2* gm = (const ulonglong2*)(g_mask + (size_t)b * TOPK * 32);
    ulonglong2* sm2 = (ulonglong2*)s_mask;
    #pragma unroll
    for (int t = 0; t < 8; t++) sm2[t * 1024 + tid] = gm[t * 1024 + tid];

    // validity is a prefix (scores sorted desc): nv = number of valid entries
    int nv = __syncthreads_count(myscore > CONF_THR);

    if (tid == 0) {
        unsigned long long rem[16];
        #pragma unroll
        for (int w = 0; w < 16; w++) rem[w] = 0ull;
        int count = 0;
        bool halt = false;
        #pragma unroll
        for (int w = 0; w < 16; w++) {
            int base = w * 64;
            if (!halt && base < nv) {
                unsigned long long valid = (nv - base >= 64)
                    ? 0xFFFFFFFFFFFFFFFFull
                    : ((1ull << (nv - base)) - 1ull);
                unsigned long long todo = valid & ~rem[w];
                while (todo) {
                    int bit = __ffsll((long long)todo) - 1;
                    int i = base + bit;
                    sel[count] = i;
                    count++;
                    if (count == MAXDET) { halt = true; break; }
                    const unsigned long long* mrow = s_mask + (size_t)i * 16;
                    #pragma unroll
                    for (int k = 0; k < 16; k++) rem[k] |= mrow[k];
                    todo &= ~(1ull << bit);
                    todo &= ~rem[w];
                }
            }
        }
        sh_count = count;
    }
    __syncthreads();
    int count = sh_count;

    float* det  = out;                                      // [B,300,6]
    float* vout = out + BATCH * MAXDET * 6;                 // [B,300]
    float* lout = vout + BATCH * MAXDET;                    // [B,300,80]

    for (int s = tid; s < MAXDET; s += 1024) {
        float d0 = 0, d1 = 0, d2 = 0, d3 = 0, d4 = 0, d5 = 0, v = 0;
        if (s < count) {
            int i   = sel[s];
            int idx = g_topk_idx[b * TOPK + i];
            const float* p = pred + ((size_t)b * NANCH + idx) * NCH;
            float cx = p[0], cy = p[1], w = p[2], h = p[3];
            float hw = __fmul_rn(w, 0.5f), hh = __fmul_rn(h, 0.5f);
            d0 = __fsub_rn(cx, hw); d1 = __fsub_rn(cy, hh);
            d2 = __fadd_rn(cx, hw); d3 = __fadd_rn(cy, hh);
            d4 = s_score[i];
            d5 = (float)g_cls[(size_t)b * NANCH + idx];
            v = 1.0f;
        }
        float* dr = det + ((size_t)b * MAXDET + s) * 6;
        dr[0] = d0; dr[1] = d1; dr[2] = d2; dr[3] = d3; dr[4] = d4; dr[5] = d5;
        vout[b * MAXDET + s] = v;
    }

    for (int e = tid; e < MAXDET * NCLS; e += 1024) {
        int s = e / NCLS, c = e % NCLS;
        float v = 0.0f;
        if (s < count) {
            int i   = sel[s];
            int idx = g_topk_idx[b * TOPK + i];
            v = logits[((size_t)b * NANCH + idx) * NCLS + c];
        }
        lout[((size_t)b * MAXDET + s) * NCLS + c] = v;
    }
}

// ---------------- launch --------------------------------------------------------
extern "C" void kernel_launch(void* const* d_in, const int* in_sizes, int n_in,
                              void* d_out, int out_size) {
    (void)in_sizes; (void)n_in; (void)out_size;
    const float* pred   = (const float*)d_in[0];
    const float* logits = (const float*)d_in[1];
    float* out = (float*)d_out;

    const int KOUT_SMEM = TOPK * 16 * (int)sizeof(unsigned long long) + TOPK * (int)sizeof(float);
    cudaFuncSetAttribute(k_out, cudaFuncAttributeMaxDynamicSharedMemorySize, KOUT_SMEM);

    int nxblocks = (NANCH + APB - 1) / APB;          // 197
    k_score<<<dim3(nxblocks, BATCH), 256>>>(pred);
    k_select<<<BATCH, 1024>>>(pred);
    k_mask<<<dim3(BATCH, 8), 1024>>>();
    k_out<<<BATCH, 1024, KOUT_SMEM>>>(pred, logits, out);
}